// round 12
// baseline (speedup 1.0000x reference)
#include <cuda_runtime.h>
#include <math.h>

#define BB 4096
#define DD 128
#define G4 512          // 4 gates * D
#define NPROJ 532       // 500 rel rows + 32 tem rows
#define ROWS 32         // batch rows per block
#define KC 8
#define NCH (DD / KC)   // 16

// Scratch (allocation-free: device global). ~1MB, L2-resident.
__device__ float g_proj[NPROJ * G4];

__device__ __forceinline__ float fast_sig(float x) {
    return 1.f / (1.f + __expf(-x));
}
__device__ __forceinline__ float fast_tanh(float x) {
    return fmaf(2.f, fast_sig(2.f * x), -1.f);
}
__device__ __forceinline__ unsigned long long pack2(float lo, float hi) {
    unsigned long long r;
    asm("mov.b64 %0, {%1, %2};" : "=l"(r) : "r"(__float_as_uint(lo)), "r"(__float_as_uint(hi)));
    return r;
}
__device__ __forceinline__ void fma2(unsigned long long& d, unsigned long long a, unsigned long long b) {
    asm("fma.rn.f32x2 %0, %1, %2, %0;" : "+l"(d) : "l"(a), "l"(b));
}
__device__ __forceinline__ float lo2(unsigned long long v) {
    return __uint_as_float((unsigned int)v);
}
__device__ __forceinline__ float hi2(unsigned long long v) {
    return __uint_as_float((unsigned int)(v >> 32));
}

// ---------------------------------------------------------------------------
// proj_kernel: g_proj[r][c] = emb_row(r) . W_ih[c] + b_ih[c] + b_hh[c]
// rows 0..499 = rel_emb, rows 500..531 = tem_emb.  ~35 MMAC.
// ---------------------------------------------------------------------------
__global__ __launch_bounds__(256) void proj_kernel(
    const float* __restrict__ W_ih,
    const float* __restrict__ rel_emb,
    const float* __restrict__ tem_emb,
    const float* __restrict__ b_ih,
    const float* __restrict__ b_hh)
{
    __shared__ float As[DD][36];
    __shared__ float Bs[DD][36];
    __shared__ const float* rowptr[32];

    const int tid = threadIdx.x;
    const int m0 = blockIdx.x * 32;
    const int n0 = blockIdx.y * 32;

    if (tid < 32) {
        int r = m0 + tid;
        if (r >= NPROJ) r = 0;
        rowptr[tid] = (r < 500) ? (rel_emb + (size_t)r * DD)
                                : (tem_emb + (size_t)(r - 500) * DD);
    }
    __syncthreads();

#pragma unroll
    for (int q = 0; q < 4; q++) {
        int f4i = tid * 4 + q;
        int row = f4i >> 5;
        int kk  = (f4i & 31) << 2;
        float4 v = *(const float4*)(rowptr[row] + kk);
        As[kk + 0][row] = v.x; As[kk + 1][row] = v.y;
        As[kk + 2][row] = v.z; As[kk + 3][row] = v.w;
    }
#pragma unroll
    for (int q = 0; q < 4; q++) {
        int f4i = tid * 4 + q;
        int col = f4i >> 5;
        int kk  = (f4i & 31) << 2;
        float4 v = *(const float4*)(W_ih + (size_t)(n0 + col) * DD + kk);
        Bs[kk + 0][col] = v.x; Bs[kk + 1][col] = v.y;
        Bs[kk + 2][col] = v.z; Bs[kk + 3][col] = v.w;
    }
    __syncthreads();

    const int ty = tid >> 4, tx = tid & 15;
    const int row0 = ty * 2, col0 = tx * 2;

    float acc[2][2] = {{0.f, 0.f}, {0.f, 0.f}};
#pragma unroll
    for (int k = 0; k < DD; k++) {
        float a0 = As[k][row0], a1 = As[k][row0 + 1];
        float2 b = *(const float2*)&Bs[k][col0];
        acc[0][0] = fmaf(a0, b.x, acc[0][0]);
        acc[0][1] = fmaf(a0, b.y, acc[0][1]);
        acc[1][0] = fmaf(a1, b.x, acc[1][0]);
        acc[1][1] = fmaf(a1, b.y, acc[1][1]);
    }

    float bia0 = b_ih[n0 + col0]     + b_hh[n0 + col0];
    float bia1 = b_ih[n0 + col0 + 1] + b_hh[n0 + col0 + 1];
#pragma unroll
    for (int r = 0; r < 2; r++) {
        int m = m0 + row0 + r;
        if (m < NPROJ) {
            float2 o = {acc[r][0] + bia0, acc[r][1] + bia1};
            *(float2*)&g_proj[(size_t)m * G4 + n0 + col0] = o;
        }
    }
}

// ---------------------------------------------------------------------------
// Fused LSTM + score kernel. grid=128 (32 rows each), block=512 (16 warps).
// Thread (ty=tid/64, tx=tid%64): rows ty*4..+3, cols j0=2tx, j0+1 (all 4 gates).
// h lives in As (transposed [d][row]) in smem; c lives in registers.
// GEMM uses packed fma.rn.f32x2 (2 MACs/instr).
// ---------------------------------------------------------------------------
__global__ __launch_bounds__(512) void lstm_fused_kernel(
    const float* __restrict__ W_hh,
    const int* __restrict__ pos_r,
    const int* __restrict__ pos_tem,
    const int* __restrict__ pos_h, const int* __restrict__ pos_t,
    const int* __restrict__ neg_h, const int* __restrict__ neg_t,
    const float* __restrict__ ent,
    float* __restrict__ out)
{
    __shared__ float As[DD][ROWS + 4];   // h transposed; overlaid by hbuf at score
    __shared__ float Bs[KC][G4 + 4];     // W_hh chunk [k][col]
    __shared__ int   trow[4][ROWS];
    __shared__ int   ridx[ROWS];

    const int tid = threadIdx.x;
    const int m0  = blockIdx.x * ROWS;
    const int tx  = tid & 63;
    const int ty  = tid >> 6;            // 0..7
    const int row0 = ty * 4;
    const int j0   = 2 * tx;

    if (tid < ROWS) {
        ridx[tid] = pos_r[m0 + tid];
#pragma unroll
        for (int t = 0; t < 4; t++)
            trow[t][tid] = 500 + pos_tem[(m0 + tid) * 4 + t];
    }
    __syncthreads();

    // ---- Step 0: h = c = 0 -> gates from rel projection; write h0 into As.
    float c0[4], c1[4];                  // c for (row0+rr, j0) and (row0+rr, j0+1)
#pragma unroll
    for (int rr = 0; rr < 4; rr++) {
        const float* p = g_proj + (size_t)ridx[row0 + rr] * G4;
        float2 pi = *(const float2*)(p + j0);
        float2 pg = *(const float2*)(p + 2 * DD + j0);
        float2 po = *(const float2*)(p + 3 * DD + j0);
        float i0 = fast_sig(pi.x),  i1 = fast_sig(pi.y);
        float g0 = fast_tanh(pg.x), g1 = fast_tanh(pg.y);
        float o0 = fast_sig(po.x),  o1 = fast_sig(po.y);
        c0[rr] = i0 * g0; c1[rr] = i1 * g1;
        As[j0    ][row0 + rr] = o0 * fast_tanh(c0[rr]);
        As[j0 + 1][row0 + rr] = o1 * fast_tanh(c1[rr]);
    }

    // First W_hh chunk, preloaded once, reused at every step (W is step-invariant).
    const float* wrow = W_hh + (size_t)tid * DD;   // thread owns column `tid`
    const float4 w0a = *(const float4*)(wrow);
    const float4 w0b = *(const float4*)(wrow + 4);

    float2 hfin0[4], hfin1[4];           // final h (step 4) per row, packed at end

    for (int t = 1; t <= 4; t++) {
        unsigned long long acc[4][4];    // acc[rr][gate] packed (j0, j0+1)
#pragma unroll
        for (int r = 0; r < 4; r++)
#pragma unroll
            for (int g = 0; g < 4; g++) acc[r][g] = 0ull;

        float4 bva = w0a, bvb = w0b;

        for (int ch = 0; ch < NCH; ch++) {
            __syncthreads();             // Bs consumed / As(h) writes visible
            Bs[0][tid] = bva.x; Bs[1][tid] = bva.y;
            Bs[2][tid] = bva.z; Bs[3][tid] = bva.w;
            Bs[4][tid] = bvb.x; Bs[5][tid] = bvb.y;
            Bs[6][tid] = bvb.z; Bs[7][tid] = bvb.w;
            __syncthreads();
            if (ch + 1 < NCH) {
                int k0 = (ch + 1) * KC;
                bva = *(const float4*)(wrow + k0);
                bvb = *(const float4*)(wrow + k0 + 4);
            }
#pragma unroll
            for (int kk = 0; kk < KC; kk++) {
                int k = ch * KC + kk;
                float4 a4 = *(const float4*)&As[k][row0];    // warp-broadcast
                unsigned long long a2[4];
                a2[0] = pack2(a4.x, a4.x);
                a2[1] = pack2(a4.y, a4.y);
                a2[2] = pack2(a4.z, a4.z);
                a2[3] = pack2(a4.w, a4.w);
#pragma unroll
                for (int g = 0; g < 4; g++) {
                    unsigned long long b2 =
                        *(const unsigned long long*)&Bs[kk][g * DD + j0];
                    fma2(acc[0][g], a2[0], b2);
                    fma2(acc[1][g], a2[1], b2);
                    fma2(acc[2][g], a2[2], b2);
                    fma2(acc[3][g], a2[3], b2);
                }
            }
        }

        // ---- Fused epilogue: + xg gather, activate, update c (regs), new h.
        float h0[4], h1[4];
#pragma unroll
        for (int rr = 0; rr < 4; rr++) {
            const float* p = g_proj + (size_t)trow[t - 1][row0 + rr] * G4;
            float2 pi = *(const float2*)(p + j0);
            float2 pf = *(const float2*)(p + DD + j0);
            float2 pg = *(const float2*)(p + 2 * DD + j0);
            float2 po = *(const float2*)(p + 3 * DD + j0);

            float i0 = fast_sig(lo2(acc[rr][0]) + pi.x);
            float i1 = fast_sig(hi2(acc[rr][0]) + pi.y);
            float f0 = fast_sig(lo2(acc[rr][1]) + pf.x);
            float f1 = fast_sig(hi2(acc[rr][1]) + pf.y);
            float g0 = fast_tanh(lo2(acc[rr][2]) + pg.x);
            float g1 = fast_tanh(hi2(acc[rr][2]) + pg.y);
            float o0 = fast_sig(lo2(acc[rr][3]) + po.x);
            float o1 = fast_sig(hi2(acc[rr][3]) + po.y);

            c0[rr] = f0 * c0[rr] + i0 * g0;
            c1[rr] = f1 * c1[rr] + i1 * g1;
            h0[rr] = o0 * fast_tanh(c0[rr]);
            h1[rr] = o1 * fast_tanh(c1[rr]);
        }

        __syncthreads();                 // all warps done reading As this step
        if (t < 4) {
#pragma unroll
            for (int rr = 0; rr < 4; rr++) {
                As[j0    ][row0 + rr] = h0[rr];
                As[j0 + 1][row0 + rr] = h1[rr];
            }
            // next iteration's first syncthreads publishes these writes
        } else {
#pragma unroll
            for (int rr = 0; rr < 4; rr++) {
                hfin0[rr] = make_float2(h0[rr], h1[rr]);
                (void)hfin1;
            }
        }
    }

    // ---- Write final h row-major into hbuf (overlays As region), then score.
    float* hbuf = &As[0][0];             // [ROWS][132] floats, fits in As (128*36)
#pragma unroll
    for (int rr = 0; rr < 4; rr++)
        *(float2*)&hbuf[(row0 + rr) * 132 + j0] = hfin0[rr];
    __syncthreads();

    const int w    = tid >> 5;           // 0..15 -> 2 rows each
    const int lane = tid & 31;
    const int d0   = lane * 4;
#pragma unroll
    for (int rsub = 0; rsub < 2; rsub++) {
        int r = w * 2 + rsub;
        int m = m0 + r;
        float4 h4 = *(const float4*)&hbuf[r * 132 + d0];
        const float4* eph = (const float4*)(ent + (size_t)pos_h[m] * DD) + lane;
        const float4* ept = (const float4*)(ent + (size_t)pos_t[m] * DD) + lane;
        const float4* enh = (const float4*)(ent + (size_t)neg_h[m] * DD) + lane;
        const float4* ent_ = (const float4*)(ent + (size_t)neg_t[m] * DD) + lane;
        float4 a = *eph, b = *ept, c = *enh, d = *ent_;
        float pos = fabsf(a.x + h4.x - b.x) + fabsf(a.y + h4.y - b.y)
                  + fabsf(a.z + h4.z - b.z) + fabsf(a.w + h4.w - b.w);
        float neg = fabsf(c.x + h4.x - d.x) + fabsf(c.y + h4.y - d.y)
                  + fabsf(c.z + h4.z - d.z) + fabsf(c.w + h4.w - d.w);
#pragma unroll
        for (int off = 16; off; off >>= 1) {
            pos += __shfl_down_sync(0xffffffffu, pos, off);
            neg += __shfl_down_sync(0xffffffffu, neg, off);
        }
        if (lane == 0) {
            out[m]      = pos;
            out[BB + m] = neg;
        }
    }
}

extern "C" void kernel_launch(void* const* d_in, const int* in_sizes, int n_in,
                              void* d_out, int out_size)
{
    (void)in_sizes; (void)n_in; (void)out_size;
    const int*   pos_h   = (const int*)d_in[0];
    const int*   pos_t   = (const int*)d_in[1];
    const int*   pos_r   = (const int*)d_in[2];
    const int*   pos_tem = (const int*)d_in[3];
    const int*   neg_h   = (const int*)d_in[4];
    const int*   neg_t   = (const int*)d_in[5];
    // d_in[6] neg_r, d_in[7] neg_tem unused by reference score
    const float* ent     = (const float*)d_in[8];
    const float* rel     = (const float*)d_in[9];
    const float* tem     = (const float*)d_in[10];
    const float* W_ih    = (const float*)d_in[11];
    const float* W_hh    = (const float*)d_in[12];
    const float* b_ih    = (const float*)d_in[13];
    const float* b_hh    = (const float*)d_in[14];
    float* out = (float*)d_out;

    // 1) Project the tables (532 rows), not the batch.
    dim3 gproj((NPROJ + 31) / 32, G4 / 32);
    proj_kernel<<<gproj, 256>>>(W_ih, rel, tem, b_ih, b_hh);

    // 2) Everything else in one fused kernel: step0 + 4 rec steps + scoring.
    lstm_fused_kernel<<<BB / ROWS, 512>>>(W_hh, pos_r, pos_tem,
                                          pos_h, pos_t, neg_h, neg_t,
                                          ent, out);
}

// round 13
// speedup vs baseline: 1.0041x; 1.0041x over previous
#include <cuda_runtime.h>
#include <math.h>

#define BB 4096
#define DD 128
#define G4 512          // 4 gates * D
#define NPROJ 532       // 500 rel rows + 32 tem rows
#define ROWS 32         // batch rows per block
#define KC 8
#define NCH (DD / KC)   // 16

// Scratch (allocation-free: device global). ~1MB, L2-resident.
__device__ float g_proj[NPROJ * G4];

__device__ __forceinline__ float fast_sig(float x) {
    return 1.f / (1.f + __expf(-x));
}
__device__ __forceinline__ float fast_tanh(float x) {
    return fmaf(2.f, fast_sig(2.f * x), -1.f);
}
__device__ __forceinline__ unsigned long long pack2(float lo, float hi) {
    unsigned long long r;
    asm("mov.b64 %0, {%1, %2};" : "=l"(r) : "r"(__float_as_uint(lo)), "r"(__float_as_uint(hi)));
    return r;
}
__device__ __forceinline__ void fma2(unsigned long long& d, unsigned long long a, unsigned long long b) {
    asm("fma.rn.f32x2 %0, %1, %2, %0;" : "+l"(d) : "l"(a), "l"(b));
}
__device__ __forceinline__ float lo2(unsigned long long v) {
    return __uint_as_float((unsigned int)v);
}
__device__ __forceinline__ float hi2(unsigned long long v) {
    return __uint_as_float((unsigned int)(v >> 32));
}

// ---------------------------------------------------------------------------
// proj_kernel: g_proj[r][c] = emb_row(r) . W_ih[c] + b_ih[c] + b_hh[c]
// rows 0..499 = rel_emb, rows 500..531 = tem_emb.  ~35 MMAC.
// ---------------------------------------------------------------------------
__global__ __launch_bounds__(256) void proj_kernel(
    const float* __restrict__ W_ih,
    const float* __restrict__ rel_emb,
    const float* __restrict__ tem_emb,
    const float* __restrict__ b_ih,
    const float* __restrict__ b_hh)
{
    __shared__ float As[DD][36];
    __shared__ float Bs[DD][36];
    __shared__ const float* rowptr[32];

    const int tid = threadIdx.x;
    const int m0 = blockIdx.x * 32;
    const int n0 = blockIdx.y * 32;

    if (tid < 32) {
        int r = m0 + tid;
        if (r >= NPROJ) r = 0;
        rowptr[tid] = (r < 500) ? (rel_emb + (size_t)r * DD)
                                : (tem_emb + (size_t)(r - 500) * DD);
    }
    __syncthreads();

#pragma unroll
    for (int q = 0; q < 4; q++) {
        int f4i = tid * 4 + q;
        int row = f4i >> 5;
        int kk  = (f4i & 31) << 2;
        float4 v = *(const float4*)(rowptr[row] + kk);
        As[kk + 0][row] = v.x; As[kk + 1][row] = v.y;
        As[kk + 2][row] = v.z; As[kk + 3][row] = v.w;
    }
#pragma unroll
    for (int q = 0; q < 4; q++) {
        int f4i = tid * 4 + q;
        int col = f4i >> 5;
        int kk  = (f4i & 31) << 2;
        float4 v = *(const float4*)(W_ih + (size_t)(n0 + col) * DD + kk);
        Bs[kk + 0][col] = v.x; Bs[kk + 1][col] = v.y;
        Bs[kk + 2][col] = v.z; Bs[kk + 3][col] = v.w;
    }
    __syncthreads();

    const int ty = tid >> 4, tx = tid & 15;
    const int row0 = ty * 2, col0 = tx * 2;

    float acc[2][2] = {{0.f, 0.f}, {0.f, 0.f}};
#pragma unroll
    for (int k = 0; k < DD; k++) {
        float a0 = As[k][row0], a1 = As[k][row0 + 1];
        float2 b = *(const float2*)&Bs[k][col0];
        acc[0][0] = fmaf(a0, b.x, acc[0][0]);
        acc[0][1] = fmaf(a0, b.y, acc[0][1]);
        acc[1][0] = fmaf(a1, b.x, acc[1][0]);
        acc[1][1] = fmaf(a1, b.y, acc[1][1]);
    }

    float bia0 = b_ih[n0 + col0]     + b_hh[n0 + col0];
    float bia1 = b_ih[n0 + col0 + 1] + b_hh[n0 + col0 + 1];
#pragma unroll
    for (int r = 0; r < 2; r++) {
        int m = m0 + row0 + r;
        if (m < NPROJ) {
            float2 o = {acc[r][0] + bia0, acc[r][1] + bia1};
            *(float2*)&g_proj[(size_t)m * G4 + n0 + col0] = o;
        }
    }
}

// ---------------------------------------------------------------------------
// Fused LSTM + score kernel. grid=128 (32 rows each), block=512 (16 warps).
// Thread (ty=tid/64, tx=tid%64): rows ty*4..+3, cols j0=2tx, j0+1 (all 4 gates).
// h lives in As (transposed [d][row]) in smem; c lives in registers.
// GEMM uses packed fma.rn.f32x2 (2 MACs/instr).
// ---------------------------------------------------------------------------
__global__ __launch_bounds__(512) void lstm_fused_kernel(
    const float* __restrict__ W_hh,
    const int* __restrict__ pos_r,
    const int* __restrict__ pos_tem,
    const int* __restrict__ pos_h, const int* __restrict__ pos_t,
    const int* __restrict__ neg_h, const int* __restrict__ neg_t,
    const float* __restrict__ ent,
    float* __restrict__ out)
{
    __shared__ float As[DD][ROWS + 4];   // h transposed; overlaid by hbuf at score
    __shared__ float Bs[KC][G4 + 4];     // W_hh chunk [k][col]
    __shared__ int   trow[4][ROWS];
    __shared__ int   ridx[ROWS];

    const int tid = threadIdx.x;
    const int m0  = blockIdx.x * ROWS;
    const int tx  = tid & 63;
    const int ty  = tid >> 6;            // 0..7
    const int row0 = ty * 4;
    const int j0   = 2 * tx;

    if (tid < ROWS) {
        ridx[tid] = pos_r[m0 + tid];
#pragma unroll
        for (int t = 0; t < 4; t++)
            trow[t][tid] = 500 + pos_tem[(m0 + tid) * 4 + t];
    }
    __syncthreads();

    // ---- Step 0: h = c = 0 -> gates from rel projection; write h0 into As.
    float c0[4], c1[4];                  // c for (row0+rr, j0) and (row0+rr, j0+1)
#pragma unroll
    for (int rr = 0; rr < 4; rr++) {
        const float* p = g_proj + (size_t)ridx[row0 + rr] * G4;
        float2 pi = *(const float2*)(p + j0);
        float2 pg = *(const float2*)(p + 2 * DD + j0);
        float2 po = *(const float2*)(p + 3 * DD + j0);
        float i0 = fast_sig(pi.x),  i1 = fast_sig(pi.y);
        float g0 = fast_tanh(pg.x), g1 = fast_tanh(pg.y);
        float o0 = fast_sig(po.x),  o1 = fast_sig(po.y);
        c0[rr] = i0 * g0; c1[rr] = i1 * g1;
        As[j0    ][row0 + rr] = o0 * fast_tanh(c0[rr]);
        As[j0 + 1][row0 + rr] = o1 * fast_tanh(c1[rr]);
    }

    // First W_hh chunk, preloaded once, reused at every step (W is step-invariant).
    const float* wrow = W_hh + (size_t)tid * DD;   // thread owns column `tid`
    const float4 w0a = *(const float4*)(wrow);
    const float4 w0b = *(const float4*)(wrow + 4);

    float2 hfin0[4], hfin1[4];           // final h (step 4) per row, packed at end

    for (int t = 1; t <= 4; t++) {
        unsigned long long acc[4][4];    // acc[rr][gate] packed (j0, j0+1)
#pragma unroll
        for (int r = 0; r < 4; r++)
#pragma unroll
            for (int g = 0; g < 4; g++) acc[r][g] = 0ull;

        float4 bva = w0a, bvb = w0b;

        for (int ch = 0; ch < NCH; ch++) {
            __syncthreads();             // Bs consumed / As(h) writes visible
            Bs[0][tid] = bva.x; Bs[1][tid] = bva.y;
            Bs[2][tid] = bva.z; Bs[3][tid] = bva.w;
            Bs[4][tid] = bvb.x; Bs[5][tid] = bvb.y;
            Bs[6][tid] = bvb.z; Bs[7][tid] = bvb.w;
            __syncthreads();
            if (ch + 1 < NCH) {
                int k0 = (ch + 1) * KC;
                bva = *(const float4*)(wrow + k0);
                bvb = *(const float4*)(wrow + k0 + 4);
            }
#pragma unroll
            for (int kk = 0; kk < KC; kk++) {
                int k = ch * KC + kk;
                float4 a4 = *(const float4*)&As[k][row0];    // warp-broadcast
                unsigned long long a2[4];
                a2[0] = pack2(a4.x, a4.x);
                a2[1] = pack2(a4.y, a4.y);
                a2[2] = pack2(a4.z, a4.z);
                a2[3] = pack2(a4.w, a4.w);
#pragma unroll
                for (int g = 0; g < 4; g++) {
                    unsigned long long b2 =
                        *(const unsigned long long*)&Bs[kk][g * DD + j0];
                    fma2(acc[0][g], a2[0], b2);
                    fma2(acc[1][g], a2[1], b2);
                    fma2(acc[2][g], a2[2], b2);
                    fma2(acc[3][g], a2[3], b2);
                }
            }
        }

        // ---- Fused epilogue: + xg gather, activate, update c (regs), new h.
        float h0[4], h1[4];
#pragma unroll
        for (int rr = 0; rr < 4; rr++) {
            const float* p = g_proj + (size_t)trow[t - 1][row0 + rr] * G4;
            float2 pi = *(const float2*)(p + j0);
            float2 pf = *(const float2*)(p + DD + j0);
            float2 pg = *(const float2*)(p + 2 * DD + j0);
            float2 po = *(const float2*)(p + 3 * DD + j0);

            float i0 = fast_sig(lo2(acc[rr][0]) + pi.x);
            float i1 = fast_sig(hi2(acc[rr][0]) + pi.y);
            float f0 = fast_sig(lo2(acc[rr][1]) + pf.x);
            float f1 = fast_sig(hi2(acc[rr][1]) + pf.y);
            float g0 = fast_tanh(lo2(acc[rr][2]) + pg.x);
            float g1 = fast_tanh(hi2(acc[rr][2]) + pg.y);
            float o0 = fast_sig(lo2(acc[rr][3]) + po.x);
            float o1 = fast_sig(hi2(acc[rr][3]) + po.y);

            c0[rr] = f0 * c0[rr] + i0 * g0;
            c1[rr] = f1 * c1[rr] + i1 * g1;
            h0[rr] = o0 * fast_tanh(c0[rr]);
            h1[rr] = o1 * fast_tanh(c1[rr]);
        }

        __syncthreads();                 // all warps done reading As this step
        if (t < 4) {
#pragma unroll
            for (int rr = 0; rr < 4; rr++) {
                As[j0    ][row0 + rr] = h0[rr];
                As[j0 + 1][row0 + rr] = h1[rr];
            }
            // next iteration's first syncthreads publishes these writes
        } else {
#pragma unroll
            for (int rr = 0; rr < 4; rr++) {
                hfin0[rr] = make_float2(h0[rr], h1[rr]);
                (void)hfin1;
            }
        }
    }

    // ---- Write final h row-major into hbuf (overlays As region), then score.
    float* hbuf = &As[0][0];             // [ROWS][132] floats, fits in As (128*36)
#pragma unroll
    for (int rr = 0; rr < 4; rr++)
        *(float2*)&hbuf[(row0 + rr) * 132 + j0] = hfin0[rr];
    __syncthreads();

    const int w    = tid >> 5;           // 0..15 -> 2 rows each
    const int lane = tid & 31;
    const int d0   = lane * 4;
#pragma unroll
    for (int rsub = 0; rsub < 2; rsub++) {
        int r = w * 2 + rsub;
        int m = m0 + r;
        float4 h4 = *(const float4*)&hbuf[r * 132 + d0];
        const float4* eph = (const float4*)(ent + (size_t)pos_h[m] * DD) + lane;
        const float4* ept = (const float4*)(ent + (size_t)pos_t[m] * DD) + lane;
        const float4* enh = (const float4*)(ent + (size_t)neg_h[m] * DD) + lane;
        const float4* ent_ = (const float4*)(ent + (size_t)neg_t[m] * DD) + lane;
        float4 a = *eph, b = *ept, c = *enh, d = *ent_;
        float pos = fabsf(a.x + h4.x - b.x) + fabsf(a.y + h4.y - b.y)
                  + fabsf(a.z + h4.z - b.z) + fabsf(a.w + h4.w - b.w);
        float neg = fabsf(c.x + h4.x - d.x) + fabsf(c.y + h4.y - d.y)
                  + fabsf(c.z + h4.z - d.z) + fabsf(c.w + h4.w - d.w);
#pragma unroll
        for (int off = 16; off; off >>= 1) {
            pos += __shfl_down_sync(0xffffffffu, pos, off);
            neg += __shfl_down_sync(0xffffffffu, neg, off);
        }
        if (lane == 0) {
            out[m]      = pos;
            out[BB + m] = neg;
        }
    }
}

extern "C" void kernel_launch(void* const* d_in, const int* in_sizes, int n_in,
                              void* d_out, int out_size)
{
    (void)in_sizes; (void)n_in; (void)out_size;
    const int*   pos_h   = (const int*)d_in[0];
    const int*   pos_t   = (const int*)d_in[1];
    const int*   pos_r   = (const int*)d_in[2];
    const int*   pos_tem = (const int*)d_in[3];
    const int*   neg_h   = (const int*)d_in[4];
    const int*   neg_t   = (const int*)d_in[5];
    // d_in[6] neg_r, d_in[7] neg_tem unused by reference score
    const float* ent     = (const float*)d_in[8];
    const float* rel     = (const float*)d_in[9];
    const float* tem     = (const float*)d_in[10];
    const float* W_ih    = (const float*)d_in[11];
    const float* W_hh    = (const float*)d_in[12];
    const float* b_ih    = (const float*)d_in[13];
    const float* b_hh    = (const float*)d_in[14];
    float* out = (float*)d_out;

    // 1) Project the tables (532 rows), not the batch.
    dim3 gproj((NPROJ + 31) / 32, G4 / 32);
    proj_kernel<<<gproj, 256>>>(W_ih, rel, tem, b_ih, b_hh);

    // 2) Everything else in one fused kernel: step0 + 4 rec steps + scoring.
    lstm_fused_kernel<<<BB / ROWS, 512>>>(W_hh, pos_r, pos_tem,
                                          pos_h, pos_t, neg_h, neg_t,
                                          ent, out);
}

// round 17
// speedup vs baseline: 1.1117x; 1.1072x over previous
#include <cuda_runtime.h>
#include <math.h>

#define BB 4096
#define DD 128
#define G4 512          // 4 gates * D
#define NPROJ 532       // 500 rel rows + 32 tem rows
#define ROWS 32         // batch rows per block
#define KC 16
#define NCH (DD / KC)   // 8
#define BSP 516         // Bs row pitch (floats)
#define AS_PITCH 36
#define AS_FLOATS (DD * AS_PITCH)            // 4608
#define DYN_FLOATS (AS_FLOATS + KC * BSP)    // 4608 + 8256 = 12864
#define DYN_BYTES (DYN_FLOATS * 4)           // 51456 B

// Scratch (allocation-free: device global). ~1MB, L2-resident.
__device__ float g_proj[NPROJ * G4];

__device__ __forceinline__ float fast_sig(float x) {
    return 1.f / (1.f + __expf(-x));
}
__device__ __forceinline__ float fast_tanh(float x) {
    return fmaf(2.f, fast_sig(2.f * x), -1.f);
}
__device__ __forceinline__ unsigned long long pack2(float lo, float hi) {
    unsigned long long r;
    asm("mov.b64 %0, {%1, %2};" : "=l"(r) : "r"(__float_as_uint(lo)), "r"(__float_as_uint(hi)));
    return r;
}
__device__ __forceinline__ void fma2(unsigned long long& d, unsigned long long a, unsigned long long b) {
    asm("fma.rn.f32x2 %0, %1, %2, %0;" : "+l"(d) : "l"(a), "l"(b));
}
__device__ __forceinline__ float lo2(unsigned long long v) {
    return __uint_as_float((unsigned int)v);
}
__device__ __forceinline__ float hi2(unsigned long long v) {
    return __uint_as_float((unsigned int)(v >> 32));
}

// ---------------------------------------------------------------------------
// proj_kernel: g_proj[r][c] = emb_row(r) . W_ih[c] + b_ih[c] + b_hh[c]
// rows 0..499 = rel_emb, rows 500..531 = tem_emb.  ~35 MMAC.  (unchanged)
// ---------------------------------------------------------------------------
__global__ __launch_bounds__(256) void proj_kernel(
    const float* __restrict__ W_ih,
    const float* __restrict__ rel_emb,
    const float* __restrict__ tem_emb,
    const float* __restrict__ b_ih,
    const float* __restrict__ b_hh)
{
    __shared__ float As[DD][36];
    __shared__ float Bs[DD][36];
    __shared__ const float* rowptr[32];

    const int tid = threadIdx.x;
    const int m0 = blockIdx.x * 32;
    const int n0 = blockIdx.y * 32;

    if (tid < 32) {
        int r = m0 + tid;
        if (r >= NPROJ) r = 0;
        rowptr[tid] = (r < 500) ? (rel_emb + (size_t)r * DD)
                                : (tem_emb + (size_t)(r - 500) * DD);
    }
    __syncthreads();

#pragma unroll
    for (int q = 0; q < 4; q++) {
        int f4i = tid * 4 + q;
        int row = f4i >> 5;
        int kk  = (f4i & 31) << 2;
        float4 v = *(const float4*)(rowptr[row] + kk);
        As[kk + 0][row] = v.x; As[kk + 1][row] = v.y;
        As[kk + 2][row] = v.z; As[kk + 3][row] = v.w;
    }
#pragma unroll
    for (int q = 0; q < 4; q++) {
        int f4i = tid * 4 + q;
        int col = f4i >> 5;
        int kk  = (f4i & 31) << 2;
        float4 v = *(const float4*)(W_ih + (size_t)(n0 + col) * DD + kk);
        Bs[kk + 0][col] = v.x; Bs[kk + 1][col] = v.y;
        Bs[kk + 2][col] = v.z; Bs[kk + 3][col] = v.w;
    }
    __syncthreads();

    const int ty = tid >> 4, tx = tid & 15;
    const int row0 = ty * 2, col0 = tx * 2;

    float acc[2][2] = {{0.f, 0.f}, {0.f, 0.f}};
#pragma unroll
    for (int k = 0; k < DD; k++) {
        float a0 = As[k][row0], a1 = As[k][row0 + 1];
        float2 b = *(const float2*)&Bs[k][col0];
        acc[0][0] = fmaf(a0, b.x, acc[0][0]);
        acc[0][1] = fmaf(a0, b.y, acc[0][1]);
        acc[1][0] = fmaf(a1, b.x, acc[1][0]);
        acc[1][1] = fmaf(a1, b.y, acc[1][1]);
    }

    float bia0 = b_ih[n0 + col0]     + b_hh[n0 + col0];
    float bia1 = b_ih[n0 + col0 + 1] + b_hh[n0 + col0 + 1];
#pragma unroll
    for (int r = 0; r < 2; r++) {
        int m = m0 + row0 + r;
        if (m < NPROJ) {
            float2 o = {acc[r][0] + bia0, acc[r][1] + bia1};
            *(float2*)&g_proj[(size_t)m * G4 + n0 + col0] = o;
        }
    }
}

// ---------------------------------------------------------------------------
// Fused LSTM + score. grid=128 (32 rows each), block=512 (16 warps).
// EXACT R13 structure (proven passing); only change: KC=16 (8 chunks/step,
// 17 barriers/step instead of 33). As/Bs in dynamic smem (51.5 KB).
// Thread (ty=tid/64, tx=tid%64): rows ty*4..+3, cols j0=2tx,j0+1 (all 4 gates).
// h in smem (transposed), c in registers, one W column staged per thread.
// ---------------------------------------------------------------------------
__global__ __launch_bounds__(512) void lstm_fused_kernel(
    const float* __restrict__ W_hh,
    const int* __restrict__ pos_r,
    const int* __restrict__ pos_tem,
    const int* __restrict__ pos_h, const int* __restrict__ pos_t,
    const int* __restrict__ neg_h, const int* __restrict__ neg_t,
    const float* __restrict__ ent,
    float* __restrict__ out)
{
    extern __shared__ __align__(16) float dyn[];
    float* Asb = dyn;                   // [DD][AS_PITCH]: h transposed [k][row]
    float* Bsb = dyn + AS_FLOATS;       // [KC][BSP]: W_hh chunk [k][col]
    __shared__ int trow[4][ROWS];
    __shared__ int ridx[ROWS];
#define AS(k, r) Asb[(k) * AS_PITCH + (r)]

    const int tid = threadIdx.x;
    const int m0  = blockIdx.x * ROWS;
    const int tx  = tid & 63;
    const int ty  = tid >> 6;            // 0..7
    const int row0 = ty * 4;
    const int j0   = 2 * tx;

    if (tid < ROWS) {
        ridx[tid] = pos_r[m0 + tid];
#pragma unroll
        for (int t = 0; t < 4; t++)
            trow[t][tid] = 500 + pos_tem[(m0 + tid) * 4 + t];
    }
    __syncthreads();

    // ---- Step 0: h = c = 0 -> gates from rel projection; write h0 into As.
    float c0[4], c1[4];
#pragma unroll
    for (int rr = 0; rr < 4; rr++) {
        const float* p = g_proj + (size_t)ridx[row0 + rr] * G4;
        float2 pi = *(const float2*)(p + j0);
        float2 pg = *(const float2*)(p + 2 * DD + j0);
        float2 po = *(const float2*)(p + 3 * DD + j0);
        float i0 = fast_sig(pi.x),  i1 = fast_sig(pi.y);
        float g0 = fast_tanh(pg.x), g1 = fast_tanh(pg.y);
        float o0 = fast_sig(po.x),  o1 = fast_sig(po.y);
        c0[rr] = i0 * g0; c1[rr] = i1 * g1;
        AS(j0,     row0 + rr) = o0 * fast_tanh(c0[rr]);
        AS(j0 + 1, row0 + rr) = o1 * fast_tanh(c1[rr]);
    }
    // (h0 writes published by the first chunk's barriers below)

    // Each thread streams ONE W_hh column (tid). First chunk saved in regs,
    // reused at every step start (W is step-invariant) — exact R13 pattern.
    const float* wrow = W_hh + (size_t)tid * DD;
    const float4 w0a = *(const float4*)(wrow);
    const float4 w0b = *(const float4*)(wrow + 4);
    const float4 w0c = *(const float4*)(wrow + 8);
    const float4 w0d = *(const float4*)(wrow + 12);

    float2 hfin[4];

    for (int t = 1; t <= 4; t++) {
        unsigned long long acc[4][4];    // acc[rr][gate] packed (j0, j0+1)
#pragma unroll
        for (int r = 0; r < 4; r++)
#pragma unroll
            for (int g = 0; g < 4; g++) acc[r][g] = 0ull;

        float4 bva = w0a, bvb = w0b, bvc = w0c, bvd = w0d;

        for (int ch = 0; ch < NCH; ch++) {
            __syncthreads();             // retire previous chunk's Bs readers
            Bsb[ 0 * BSP + tid] = bva.x; Bsb[ 1 * BSP + tid] = bva.y;
            Bsb[ 2 * BSP + tid] = bva.z; Bsb[ 3 * BSP + tid] = bva.w;
            Bsb[ 4 * BSP + tid] = bvb.x; Bsb[ 5 * BSP + tid] = bvb.y;
            Bsb[ 6 * BSP + tid] = bvb.z; Bsb[ 7 * BSP + tid] = bvb.w;
            Bsb[ 8 * BSP + tid] = bvc.x; Bsb[ 9 * BSP + tid] = bvc.y;
            Bsb[10 * BSP + tid] = bvc.z; Bsb[11 * BSP + tid] = bvc.w;
            Bsb[12 * BSP + tid] = bvd.x; Bsb[13 * BSP + tid] = bvd.y;
            Bsb[14 * BSP + tid] = bvd.z; Bsb[15 * BSP + tid] = bvd.w;
            __syncthreads();             // publish Bs (and step-boundary As)

            if (ch + 1 < NCH) {          // guarded prefetch, R13-style
                int k0 = (ch + 1) * KC;
                bva = *(const float4*)(wrow + k0);
                bvb = *(const float4*)(wrow + k0 + 4);
                bvc = *(const float4*)(wrow + k0 + 8);
                bvd = *(const float4*)(wrow + k0 + 12);
            }

            const int kbase = ch * KC;
#pragma unroll
            for (int kk = 0; kk < KC; kk++) {
                float4 a4 = *(const float4*)&AS(kbase + kk, row0);  // warp-broadcast
                unsigned long long a2[4];
                a2[0] = pack2(a4.x, a4.x);
                a2[1] = pack2(a4.y, a4.y);
                a2[2] = pack2(a4.z, a4.z);
                a2[3] = pack2(a4.w, a4.w);
#pragma unroll
                for (int g = 0; g < 4; g++) {
                    unsigned long long b2 =
                        *(const unsigned long long*)&Bsb[kk * BSP + g * DD + j0];
                    fma2(acc[0][g], a2[0], b2);
                    fma2(acc[1][g], a2[1], b2);
                    fma2(acc[2][g], a2[2], b2);
                    fma2(acc[3][g], a2[3], b2);
                }
            }
        }

        // ---- Fused epilogue: + xg gather, activate, update c (regs), new h.
        float h0[4], h1[4];
#pragma unroll
        for (int rr = 0; rr < 4; rr++) {
            const float* p = g_proj + (size_t)trow[t - 1][row0 + rr] * G4;
            float2 pi = *(const float2*)(p + j0);
            float2 pf = *(const float2*)(p + DD + j0);
            float2 pg = *(const float2*)(p + 2 * DD + j0);
            float2 po = *(const float2*)(p + 3 * DD + j0);

            float i0 = fast_sig(lo2(acc[rr][0]) + pi.x);
            float i1 = fast_sig(hi2(acc[rr][0]) + pi.y);
            float f0 = fast_sig(lo2(acc[rr][1]) + pf.x);
            float f1 = fast_sig(hi2(acc[rr][1]) + pf.y);
            float g0 = fast_tanh(lo2(acc[rr][2]) + pg.x);
            float g1 = fast_tanh(hi2(acc[rr][2]) + pg.y);
            float o0 = fast_sig(lo2(acc[rr][3]) + po.x);
            float o1 = fast_sig(hi2(acc[rr][3]) + po.y);

            c0[rr] = f0 * c0[rr] + i0 * g0;
            c1[rr] = f1 * c1[rr] + i1 * g1;
            h0[rr] = o0 * fast_tanh(c0[rr]);
            h1[rr] = o1 * fast_tanh(c1[rr]);
        }

        __syncthreads();                 // all As reads of this step done
        if (t < 4) {
#pragma unroll
            for (int rr = 0; rr < 4; rr++) {
                AS(j0,     row0 + rr) = h0[rr];
                AS(j0 + 1, row0 + rr) = h1[rr];
            }
            // next step's first chunk barriers publish these writes
        } else {
#pragma unroll
            for (int rr = 0; rr < 4; rr++)
                hfin[rr] = make_float2(h0[rr], h1[rr]);
        }
    }

    // ---- Final h row-major into hbuf (overlays As region), then score.
    float* hbuf = Asb;                   // [ROWS][132] floats (4224 <= 4608)
#pragma unroll
    for (int rr = 0; rr < 4; rr++)
        *(float2*)&hbuf[(row0 + rr) * 132 + j0] = hfin[rr];
    __syncthreads();

    const int w    = tid >> 5;           // 0..15 -> 2 rows each
    const int lane = tid & 31;
    const int d0   = lane * 4;
#pragma unroll
    for (int rsub = 0; rsub < 2; rsub++) {
        int r = w * 2 + rsub;
        int m = m0 + r;
        float4 h4 = *(const float4*)&hbuf[r * 132 + d0];
        const float4* eph  = (const float4*)(ent + (size_t)pos_h[m] * DD) + lane;
        const float4* ept  = (const float4*)(ent + (size_t)pos_t[m] * DD) + lane;
        const float4* enh  = (const float4*)(ent + (size_t)neg_h[m] * DD) + lane;
        const float4* ent_ = (const float4*)(ent + (size_t)neg_t[m] * DD) + lane;
        float4 a = *eph, b = *ept, c = *enh, d = *ent_;
        float pos = fabsf(a.x + h4.x - b.x) + fabsf(a.y + h4.y - b.y)
                  + fabsf(a.z + h4.z - b.z) + fabsf(a.w + h4.w - b.w);
        float neg = fabsf(c.x + h4.x - d.x) + fabsf(c.y + h4.y - d.y)
                  + fabsf(c.z + h4.z - d.z) + fabsf(c.w + h4.w - d.w);
#pragma unroll
        for (int off = 16; off; off >>= 1) {
            pos += __shfl_down_sync(0xffffffffu, pos, off);
            neg += __shfl_down_sync(0xffffffffu, neg, off);
        }
        if (lane == 0) {
            out[m]      = pos;
            out[BB + m] = neg;
        }
    }
#undef AS
}

extern "C" void kernel_launch(void* const* d_in, const int* in_sizes, int n_in,
                              void* d_out, int out_size)
{
    (void)in_sizes; (void)n_in; (void)out_size;
    const int*   pos_h   = (const int*)d_in[0];
    const int*   pos_t   = (const int*)d_in[1];
    const int*   pos_r   = (const int*)d_in[2];
    const int*   pos_tem = (const int*)d_in[3];
    const int*   neg_h   = (const int*)d_in[4];
    const int*   neg_t   = (const int*)d_in[5];
    // d_in[6] neg_r, d_in[7] neg_tem unused by reference score
    const float* ent     = (const float*)d_in[8];
    const float* rel     = (const float*)d_in[9];
    const float* tem     = (const float*)d_in[10];
    const float* W_ih    = (const float*)d_in[11];
    const float* W_hh    = (const float*)d_in[12];
    const float* b_ih    = (const float*)d_in[13];
    const float* b_hh    = (const float*)d_in[14];
    float* out = (float*)d_out;

    // Allow >48KB dynamic smem (attribute set, not an allocation; capture-safe).
    cudaFuncSetAttribute(lstm_fused_kernel,
                         cudaFuncAttributeMaxDynamicSharedMemorySize, DYN_BYTES);

    // 1) Project the tables (532 rows), not the batch.
    dim3 gproj((NPROJ + 31) / 32, G4 / 32);
    proj_kernel<<<gproj, 256>>>(W_ih, rel, tem, b_ih, b_hh);

    // 2) Fused step0 + 4 rec steps + scoring (R13 structure, KC=16).
    lstm_fused_kernel<<<BB / ROWS, 512, DYN_BYTES>>>(W_hh, pos_r, pos_tem,
                                                     pos_h, pos_t, neg_h, neg_t,
                                                     ent, out);
}